// round 8
// baseline (speedup 1.0000x reference)
#include <cuda_runtime.h>
#include <cuda_bf16.h>
#include <math.h>
#include <stdint.h>

// ---------------- problem constants ----------------
#define TOK   4096
#define HID   2048
#define NEXP  32
#define NGRP  8
#define EPG   4
#define TKG   4
#define TOPK  8
#define IDIM  1024
#define SDIM  2048
#define NROW  32768
#define ROUTED_SCALE 2.5f

// ---------------- scratch ----------------
__device__ int   g_tkidx[NROW];
__device__ float g_tkw[NROW];
__device__ int   g_counts[NEXP];
__device__ int   g_offsets[NEXP];
__device__ int   g_row_token[NROW];
__device__ int   g_inv[NROW];

__device__ float g_gate[NROW * IDIM];
__device__ float g_up  [NROW * IDIM];
__device__ float g_down[NROW * HID];
__device__ float g_sg  [TOK * SDIM];
__device__ float g_su  [TOK * SDIM];

// tf32-pre-rounded operand copies
__device__ float g_rwg[NEXP * HID * IDIM];
__device__ float g_rwu[NEXP * HID * IDIM];
__device__ float g_rwd[NEXP * IDIM * HID];
__device__ float g_rsg[HID * SDIM];
__device__ float g_rsu[HID * SDIM];
__device__ float g_rsd[SDIM * HID];
__device__ float g_rx [TOK * HID];

// ---------------- tf32 helpers ----------------
__device__ __forceinline__ uint32_t f2tf(float f) {
    uint32_t r;
    asm("cvt.rna.tf32.f32 %0, %1;" : "=r"(r) : "f"(f));
    return r;
}
__device__ __forceinline__ void mma_tf32(float* d, const uint32_t* a, const uint32_t* b)
{
    asm volatile(
        "mma.sync.aligned.m16n8k8.row.col.f32.tf32.tf32.f32 "
        "{%0,%1,%2,%3}, {%4,%5,%6,%7}, {%8,%9}, {%0,%1,%2,%3};\n"
        : "+f"(d[0]), "+f"(d[1]), "+f"(d[2]), "+f"(d[3])
        : "r"(a[0]), "r"(a[1]), "r"(a[2]), "r"(a[3]), "r"(b[0]), "r"(b[1]));
}
__device__ __forceinline__ void cp16(uint32_t dst, const void* src) {
    asm volatile("cp.async.cg.shared.global [%0], [%1], 16;" :: "r"(dst), "l"(src));
}
__device__ __forceinline__ uint32_t smem_u32(const void* p) {
    uint32_t a;
    asm("{ .reg .u64 t; cvta.to.shared.u64 t, %1; cvt.u32.u64 %0, t; }" : "=r"(a) : "l"(p));
    return a;
}
#define CP_COMMIT() asm volatile("cp.async.commit_group;" ::: "memory")
#define CP_WAIT0()  asm volatile("cp.async.wait_group 0;" ::: "memory")
#define CP_WAIT1()  asm volatile("cp.async.wait_group 1;" ::: "memory")

// ---------------- pre-round everything to tf32 ----------------
__global__ void __launch_bounds__(256)
round_all_kernel(const float* __restrict__ wg, const float* __restrict__ wu,
                 const float* __restrict__ wd, const float* __restrict__ sg,
                 const float* __restrict__ su, const float* __restrict__ sd,
                 const float* __restrict__ x)
{
    const long SZW = 16L * 1024 * 1024;
    const long SZS = 1L * 1024 * 1024;
    const long SZX = 2L * 1024 * 1024;
    const long total = 3 * SZW + 3 * SZS + SZX;
    for (long i = (long)blockIdx.x * 256 + threadIdx.x; i < total;
         i += (long)gridDim.x * 256) {
        const float4* src; uint4* dst; long j = i;
        if (j < SZW)              { src = (const float4*)wg; dst = (uint4*)g_rwg; }
        else if ((j -= SZW) < SZW){ src = (const float4*)wu; dst = (uint4*)g_rwu; }
        else if ((j -= SZW) < SZW){ src = (const float4*)wd; dst = (uint4*)g_rwd; }
        else if ((j -= SZW) < SZS){ src = (const float4*)sg; dst = (uint4*)g_rsg; }
        else if ((j -= SZS) < SZS){ src = (const float4*)su; dst = (uint4*)g_rsu; }
        else if ((j -= SZS) < SZS){ src = (const float4*)sd; dst = (uint4*)g_rsd; }
        else { j -= SZS;            src = (const float4*)x;  dst = (uint4*)g_rx;  }
        float4 v = src[j];
        dst[j] = make_uint4(f2tf(v.x), f2tf(v.y), f2tf(v.z), f2tf(v.w));
    }
}

// ---------------- router ----------------
__global__ void __launch_bounds__(128)
router_kernel(const float* __restrict__ x, const float* __restrict__ rw,
              const float* __restrict__ rbias)
{
    int t = blockIdx.x;
    __shared__ float sx[HID];
    __shared__ float spart[4][NEXP];
    __shared__ float slog[NEXP];
    int tid = threadIdx.x;
    const float4* xr = (const float4*)(x + (size_t)t * HID);
    float4* sxv = (float4*)sx;
    for (int i = tid; i < HID / 4; i += 128) sxv[i] = xr[i];
    __syncthreads();

    int w = tid >> 5, lane = tid & 31;
    float acc = 0.f;
    int h0 = w * (HID / 4);
    #pragma unroll 4
    for (int h = h0; h < h0 + HID / 4; ++h)
        acc = fmaf(sx[h], rw[h * NEXP + lane], acc);
    spart[w][lane] = acc;
    __syncthreads();
    if (tid < NEXP)
        slog[tid] = spart[0][tid] + spart[1][tid] + spart[2][tid] + spart[3][tid];
    __syncthreads();

    if (tid == 0) {
        float sc[NEXP], sb[NEXP];
        #pragma unroll
        for (int e = 0; e < NEXP; ++e) {
            float s = 1.f / (1.f + expf(-slog[e]));
            sc[e] = s;
            sb[e] = s + rbias[e];
        }
        float gs[NGRP];
        #pragma unroll
        for (int g = 0; g < NGRP; ++g) {
            float m1 = -1e30f, m2 = -1e30f;
            #pragma unroll
            for (int j = 0; j < EPG; ++j) {
                float v = sb[g * EPG + j];
                if (v > m1) { m2 = m1; m1 = v; }
                else if (v > m2) { m2 = v; }
            }
            gs[g] = m1 + m2;
        }
        bool keep[NGRP];
        #pragma unroll
        for (int g = 0; g < NGRP; ++g) keep[g] = false;
        for (int r = 0; r < TKG; ++r) {
            int bi = -1; float bv = -1e30f;
            for (int g = 0; g < NGRP; ++g)
                if (!keep[g] && gs[g] > bv) { bv = gs[g]; bi = g; }
            keep[bi] = true;
        }
        float masked[NEXP];
        #pragma unroll
        for (int e = 0; e < NEXP; ++e)
            masked[e] = keep[e >> 2] ? sb[e] : 0.0f;
        int idx[TOPK];
        for (int r = 0; r < TOPK; ++r) {
            int bi = 0; float bv = -1e30f;
            for (int e = 0; e < NEXP; ++e)
                if (masked[e] > bv) { bv = masked[e]; bi = e; }
            masked[bi] = -1e30f;
            idx[r] = bi;
        }
        float wsum = 0.f, wv[TOPK];
        #pragma unroll
        for (int r = 0; r < TOPK; ++r) { wv[r] = sc[idx[r]]; wsum += wv[r]; }
        float inv = ROUTED_SCALE / wsum;
        #pragma unroll
        for (int r = 0; r < TOPK; ++r) {
            g_tkidx[t * TOPK + r] = idx[r];
            g_tkw  [t * TOPK + r] = wv[r] * inv;
        }
    }
}

// ---------------- fused dispatch ----------------
__global__ void __launch_bounds__(1024)
dispatch_kernel()
{
    __shared__ int sc[NEXP], so[NEXP], scur[NEXP];
    int tid = threadIdx.x;
    if (tid < NEXP) { sc[tid] = 0; scur[tid] = 0; }
    __syncthreads();
    for (int i = tid; i < NROW; i += 1024)
        atomicAdd(&sc[g_tkidx[i]], 1);
    __syncthreads();
    if (tid == 0) {
        int a = 0;
        #pragma unroll
        for (int e = 0; e < NEXP; ++e) { so[e] = a; a += sc[e]; }
    }
    __syncthreads();
    for (int i = tid; i < NROW; i += 1024) {
        int e = g_tkidx[i];
        int pos = so[e] + atomicAdd(&scur[e], 1);
        g_row_token[pos] = i >> 3;
        g_inv[i] = pos;
    }
    if (tid < NEXP) { g_counts[tid] = sc[tid]; g_offsets[tid] = so[tid]; }
}

// ---------------- tf32 tensor-core GEMM ----------------
// 512 threads = 16 warps (4/SMSP), block 256x128x32, warp tile 64x32.
// 3-stage cp.async pipeline; operands pre-rounded to tf32 in gmem.
#define BM 256
#define BN 128
#define BK 32
#define AS_STRIDE 36
#define AS_BUF (BM * AS_STRIDE)      // 9216 words
#define BS_BUF (BK * BN)             // 4096 words
#define NSTAGE 3
#define GEMM_SMEM_W (256 + NSTAGE * (AS_BUF + BS_BUF))   // 40192 w = 160768 B

__global__ void __launch_bounds__(512)
tmma_kernel(const float* __restrict__ A,
            const float* __restrict__ B1p, const float* __restrict__ B2p,
            float* __restrict__ C1p, float* __restrict__ C2p,
            int Nhalf, int Kd, int grouped, int gather, int Mtotal)
{
    extern __shared__ uint32_t smu[];
    int* sArow = (int*)smu;
    uint32_t* Asb = smu + 256;
    uint32_t* Bsb = smu + 256 + NSTAGE * AS_BUF;
#define AS(b, m, k)  Asb[(b) * AS_BUF + (m) * AS_STRIDE + (k)]
#define BSW(b, k, n) Bsb[(b) * BS_BUF + (k) * BN + ((n) ^ ((((k) & 3)) << 3))]

    int tid = threadIdx.x;
    int e = blockIdx.z;
    int off, cnt;
    if (grouped) { off = g_offsets[e]; cnt = g_counts[e]; }
    else         { off = 0;            cnt = Mtotal; }
    int mtile = blockIdx.y * BM;
    if (mtile >= cnt) return;

    int n0 = blockIdx.x * BN;
    const float* B0 = B1p; float* C = C1p;
    if (n0 >= Nhalf) { B0 = B2p; C = C2p; n0 -= Nhalf; }
    const int N = Nhalf;

    if (tid < 256) {
        int lr = mtile + tid;
        if (lr >= cnt) lr = cnt - 1;
        int p = off + lr;
        sArow[tid] = gather ? g_row_token[p] : p;
    }
    __syncthreads();

    const float* Bg = B0 + (size_t)e * Kd * N + n0;

    // A loader: row = tid>>1 (0..255), seg = (tid&1)*16, 4 float4 each
    int ar = tid >> 1;
    int aseg = (tid & 1) * 16;
    const float* Ap0 = A + (size_t)sArow[ar] * Kd + aseg;
    // B loader: k rows (tid>>5) and (tid>>5)+16, float4 at col (tid&31)*4
    int bk = tid >> 5;                 // 0..15
    int bcol = (tid & 31) * 4;
    int bswz = bcol ^ ((bk & 3) << 3); // (bk+16)&3 == bk&3, same swizzle

    uint32_t sb = smem_u32(smu);
    uint32_t aA0 = sb + (256u + (uint32_t)ar * AS_STRIDE + aseg) * 4u;
    uint32_t bA  = sb + (256u + NSTAGE * AS_BUF) * 4u + ((uint32_t)bk * BN + bswz) * 4u;
    const float* Bp = Bg + (size_t)bk * N + bcol;
    const size_t bstep16 = (size_t)16 * N;

    int numK = Kd >> 5;

    // prologue: stages 0,1
    #pragma unroll
    for (int s = 0; s < 2; ++s) {
        int ko = s << 5;
        #pragma unroll
        for (int j = 0; j < 4; ++j)
            cp16(aA0 + (uint32_t)s * AS_BUF * 4 + j * 16, Ap0 + ko + j * 4);
        cp16(bA + (uint32_t)s * BS_BUF * 4, Bp + ko * (size_t)N);
        cp16(bA + (uint32_t)s * BS_BUF * 4 + 16u * BN * 4, Bp + ko * (size_t)N + bstep16);
        CP_COMMIT();
    }

    int wid = tid >> 5, lane = tid & 31;
    int wm = wid >> 2, wn = wid & 3;   // warp tile: rows wm*64, cols wn*32
    int g = lane >> 2, tg = lane & 3;

    float acc[4][4][4];
    #pragma unroll
    for (int mi = 0; mi < 4; ++mi)
        #pragma unroll
        for (int ni = 0; ni < 4; ++ni)
            #pragma unroll
            for (int c = 0; c < 4; ++c) acc[mi][ni][c] = 0.f;

    int buf = 0, nbuf = 2;
    for (int t = 0; t < numK; ++t) {
        if (t + 1 < numK) { CP_WAIT1(); } else { CP_WAIT0(); }
        __syncthreads();
        if (t + 2 < numK) {
            int ko = (t + 2) << 5;
            #pragma unroll
            for (int j = 0; j < 4; ++j)
                cp16(aA0 + (uint32_t)nbuf * AS_BUF * 4 + j * 16, Ap0 + ko + j * 4);
            cp16(bA + (uint32_t)nbuf * BS_BUF * 4, Bp + ko * (size_t)N);
            cp16(bA + (uint32_t)nbuf * BS_BUF * 4 + 16u * BN * 4,
                 Bp + ko * (size_t)N + bstep16);
            CP_COMMIT();
        }
        #pragma unroll
        for (int kk = 0; kk < 4; ++kk) {
            int k8 = kk * 8;
            uint32_t af[4][4];
            #pragma unroll
            for (int mi = 0; mi < 4; ++mi) {
                int r0 = wm * 64 + mi * 16 + g;
                af[mi][0] = AS(buf, r0,     k8 + tg);
                af[mi][1] = AS(buf, r0 + 8, k8 + tg);
                af[mi][2] = AS(buf, r0,     k8 + tg + 4);
                af[mi][3] = AS(buf, r0 + 8, k8 + tg + 4);
            }
            uint32_t bf[4][2];
            #pragma unroll
            for (int ni = 0; ni < 4; ++ni) {
                int nn = wn * 32 + ni * 8 + g;
                bf[ni][0] = BSW(buf, k8 + tg,     nn);
                bf[ni][1] = BSW(buf, k8 + tg + 4, nn);
            }
            #pragma unroll
            for (int mi = 0; mi < 4; ++mi)
                #pragma unroll
                for (int ni = 0; ni < 4; ++ni)
                    mma_tf32(acc[mi][ni], af[mi], bf[ni]);
        }
        if (++buf == NSTAGE) buf = 0;
        if (++nbuf == NSTAGE) nbuf = 0;
    }

    // epilogue
    #pragma unroll
    for (int mi = 0; mi < 4; ++mi) {
        int lr0 = mtile + wm * 64 + mi * 16 + g;
        #pragma unroll
        for (int ni = 0; ni < 4; ++ni) {
            int col = n0 + wn * 32 + ni * 8 + tg * 2;
            if (lr0 < cnt)
                *(float2*)(C + (size_t)(off + lr0) * N + col) =
                    make_float2(acc[mi][ni][0], acc[mi][ni][1]);
            if (lr0 + 8 < cnt)
                *(float2*)(C + (size_t)(off + lr0 + 8) * N + col) =
                    make_float2(acc[mi][ni][2], acc[mi][ni][3]);
        }
    }
#undef AS
#undef BSW
}

// ---------------- SwiGLU elementwise -> tf32-rounded output ----------------
__global__ void silu_mul_round_kernel(float* __restrict__ g, const float* __restrict__ u,
                                      long n4)
{
    long i = (long)blockIdx.x * blockDim.x + threadIdx.x;
    long stride = (long)gridDim.x * blockDim.x;
    uint4* gv = (uint4*)g;
    const float4* gf = (const float4*)g;
    const float4* uv = (const float4*)u;
    for (; i < n4; i += stride) {
        float4 gg = gf[i];
        float4 uu = uv[i];
        float vx = gg.x / (1.f + __expf(-gg.x)) * uu.x;
        float vy = gg.y / (1.f + __expf(-gg.y)) * uu.y;
        float vz = gg.z / (1.f + __expf(-gg.z)) * uu.z;
        float vw = gg.w / (1.f + __expf(-gg.w)) * uu.w;
        gv[i] = make_uint4(f2tf(vx), f2tf(vy), f2tf(vz), f2tf(vw));
    }
}

// ---------------- combine ----------------
__global__ void combine_kernel(const float* __restrict__ down, float* __restrict__ out)
{
    int t = blockIdx.x;
    int tid = threadIdx.x;
    int   pidx[TOPK];
    float pw[TOPK];
    #pragma unroll
    for (int k = 0; k < TOPK; ++k) {
        pidx[k] = g_inv[t * TOPK + k];
        pw[k]   = g_tkw[t * TOPK + k];
    }
    const int H4 = HID / 4;
    float4* ov = (float4*)out;
    const float4* dv = (const float4*)down;
    for (int i = tid; i < H4; i += 256) {
        float4 o = ov[(size_t)t * H4 + i];
        #pragma unroll
        for (int k = 0; k < TOPK; ++k) {
            float4 v = dv[(size_t)pidx[k] * H4 + i];
            float w = pw[k];
            o.x = fmaf(w, v.x, o.x);
            o.y = fmaf(w, v.y, o.y);
            o.z = fmaf(w, v.z, o.z);
            o.w = fmaf(w, v.w, o.w);
        }
        ov[(size_t)t * H4 + i] = o;
    }
}

// ---------------- launch ----------------
static float* symf(const void* sym) {
    void* p = nullptr;
    cudaGetSymbolAddress(&p, sym);
    return (float*)p;
}

extern "C" void kernel_launch(void* const* d_in, const int* in_sizes, int n_in,
                              void* d_out, int out_size)
{
    const float* x       = (const float*)d_in[0];
    const float* rw      = (const float*)d_in[1];
    const float* rbias   = (const float*)d_in[2];
    const float* w_gate  = (const float*)d_in[3];
    const float* w_up    = (const float*)d_in[4];
    const float* w_down  = (const float*)d_in[5];
    const float* sw_gate = (const float*)d_in[6];
    const float* sw_up   = (const float*)d_in[7];
    const float* sw_down = (const float*)d_in[8];
    float* out = (float*)d_out;

    float* p_gate = symf(g_gate);
    float* p_up   = symf(g_up);
    float* p_down = symf(g_down);
    float* p_sg   = symf(g_sg);
    float* p_su   = symf(g_su);
    float* p_rwg  = symf(g_rwg);
    float* p_rwu  = symf(g_rwu);
    float* p_rwd  = symf(g_rwd);
    float* p_rsg  = symf(g_rsg);
    float* p_rsu  = symf(g_rsu);
    float* p_rsd  = symf(g_rsd);
    float* p_rx   = symf(g_rx);

    const int SMB = GEMM_SMEM_W * 4;
    cudaFuncSetAttribute(tmma_kernel, cudaFuncAttributeMaxDynamicSharedMemorySize, SMB);

    // 0) pre-round all GEMM operands
    round_all_kernel<<<2048, 256>>>(w_gate, w_up, w_down, sw_gate, sw_up, sw_down, x);

    // 1) router + dispatch
    router_kernel<<<TOK, 128>>>(x, rw, rbias);
    dispatch_kernel<<<1, 1024>>>();

    // 2) routed gate+up fused (A gathered from rounded x), N=1024 each
    tmma_kernel<<<dim3(16, 16, NEXP), 512, SMB>>>(
        p_rx, p_rwg, p_rwu, p_gate, p_up, IDIM, HID, 1, 1, 0);

    // 3) SwiGLU (rounded output, in place)
    silu_mul_round_kernel<<<2048, 256>>>(p_gate, p_up, (long)NROW * IDIM / 4);

    // 4) routed down: N=2048, K=1024  (ncu launch #5)
    tmma_kernel<<<dim3(16, 16, NEXP), 512, SMB>>>(
        p_gate, p_rwd, p_rwd, p_down, p_down, HID, IDIM, 1, 0, 0);

    // 5) shared gate+up fused: N=2048 each
    tmma_kernel<<<dim3(32, 16, 1), 512, SMB>>>(
        p_rx, p_rsg, p_rsu, p_sg, p_su, SDIM, HID, 0, 0, TOK);
    silu_mul_round_kernel<<<2048, 256>>>(p_sg, p_su, (long)TOK * SDIM / 4);
    tmma_kernel<<<dim3(16, 16, 1), 512, SMB>>>(
        p_sg, p_rsd, p_rsd, out, out, HID, SDIM, 0, 0, TOK);

    // 6) weighted combine
    combine_kernel<<<TOK, 256>>>(p_down, out);
}

// round 9
// speedup vs baseline: 1.0687x; 1.0687x over previous
#include <cuda_runtime.h>
#include <cuda_bf16.h>
#include <math.h>
#include <stdint.h>

// ---------------- problem constants ----------------
#define TOK   4096
#define HID   2048
#define NEXP  32
#define NGRP  8
#define EPG   4
#define TKG   4
#define TOPK  8
#define IDIM  1024
#define SDIM  2048
#define NROW  32768
#define ROUTED_SCALE 2.5f

// ---------------- scratch ----------------
__device__ int   g_tkidx[NROW];
__device__ float g_tkw[NROW];
__device__ int   g_counts[NEXP];
__device__ int   g_offsets[NEXP];
__device__ int   g_row_token[NROW];
__device__ int   g_inv[NROW];

__device__ float g_gate[NROW * IDIM];
__device__ float g_up  [NROW * IDIM];
__device__ float g_down[NROW * HID];
__device__ float g_sg  [TOK * SDIM];
__device__ float g_su  [TOK * SDIM];

// tf32-pre-rounded operand copies
__device__ float g_rwg[NEXP * HID * IDIM];
__device__ float g_rwu[NEXP * HID * IDIM];
__device__ float g_rwd[NEXP * IDIM * HID];
__device__ float g_rsg[HID * SDIM];
__device__ float g_rsu[HID * SDIM];
__device__ float g_rsd[SDIM * HID];
__device__ float g_rx [TOK * HID];

// ---------------- tf32 helpers ----------------
__device__ __forceinline__ uint32_t f2tf(float f) {
    uint32_t r;
    asm("cvt.rna.tf32.f32 %0, %1;" : "=r"(r) : "f"(f));
    return r;
}
__device__ __forceinline__ void mma_tf32(float* d, const uint32_t* a, const uint32_t* b)
{
    asm volatile(
        "mma.sync.aligned.m16n8k8.row.col.f32.tf32.tf32.f32 "
        "{%0,%1,%2,%3}, {%4,%5,%6,%7}, {%8,%9}, {%0,%1,%2,%3};\n"
        : "+f"(d[0]), "+f"(d[1]), "+f"(d[2]), "+f"(d[3])
        : "r"(a[0]), "r"(a[1]), "r"(a[2]), "r"(a[3]), "r"(b[0]), "r"(b[1]));
}
__device__ __forceinline__ void ldsm4(uint32_t* r, uint32_t addr)
{
    asm volatile("ldmatrix.sync.aligned.m8n8.x4.shared.b16 {%0,%1,%2,%3}, [%4];"
        : "=r"(r[0]), "=r"(r[1]), "=r"(r[2]), "=r"(r[3]) : "r"(addr));
}
__device__ __forceinline__ void cp16(uint32_t dst, const void* src) {
    asm volatile("cp.async.cg.shared.global [%0], [%1], 16;" :: "r"(dst), "l"(src));
}
__device__ __forceinline__ uint32_t smem_u32(const void* p) {
    uint32_t a;
    asm("{ .reg .u64 t; cvta.to.shared.u64 t, %1; cvt.u32.u64 %0, t; }" : "=r"(a) : "l"(p));
    return a;
}
#define CP_COMMIT() asm volatile("cp.async.commit_group;" ::: "memory")
#define CP_WAIT0()  asm volatile("cp.async.wait_group 0;" ::: "memory")
#define CP_WAIT1()  asm volatile("cp.async.wait_group 1;" ::: "memory")

// ---------------- pre-round everything to tf32 ----------------
__global__ void __launch_bounds__(256)
round_all_kernel(const float* __restrict__ wg, const float* __restrict__ wu,
                 const float* __restrict__ wd, const float* __restrict__ sg,
                 const float* __restrict__ su, const float* __restrict__ sd,
                 const float* __restrict__ x)
{
    const long SZW = 16L * 1024 * 1024;
    const long SZS = 1L * 1024 * 1024;
    const long SZX = 2L * 1024 * 1024;
    const long total = 3 * SZW + 3 * SZS + SZX;
    for (long i = (long)blockIdx.x * 256 + threadIdx.x; i < total;
         i += (long)gridDim.x * 256) {
        const float4* src; uint4* dst; long j = i;
        if (j < SZW)              { src = (const float4*)wg; dst = (uint4*)g_rwg; }
        else if ((j -= SZW) < SZW){ src = (const float4*)wu; dst = (uint4*)g_rwu; }
        else if ((j -= SZW) < SZW){ src = (const float4*)wd; dst = (uint4*)g_rwd; }
        else if ((j -= SZW) < SZS){ src = (const float4*)sg; dst = (uint4*)g_rsg; }
        else if ((j -= SZS) < SZS){ src = (const float4*)su; dst = (uint4*)g_rsu; }
        else if ((j -= SZS) < SZS){ src = (const float4*)sd; dst = (uint4*)g_rsd; }
        else { j -= SZS;            src = (const float4*)x;  dst = (uint4*)g_rx;  }
        float4 v = src[j];
        dst[j] = make_uint4(f2tf(v.x), f2tf(v.y), f2tf(v.z), f2tf(v.w));
    }
}

// ---------------- router ----------------
__global__ void __launch_bounds__(128)
router_kernel(const float* __restrict__ x, const float* __restrict__ rw,
              const float* __restrict__ rbias)
{
    int t = blockIdx.x;
    __shared__ float sx[HID];
    __shared__ float spart[4][NEXP];
    __shared__ float slog[NEXP];
    int tid = threadIdx.x;
    const float4* xr = (const float4*)(x + (size_t)t * HID);
    float4* sxv = (float4*)sx;
    for (int i = tid; i < HID / 4; i += 128) sxv[i] = xr[i];
    __syncthreads();

    int w = tid >> 5, lane = tid & 31;
    float acc = 0.f;
    int h0 = w * (HID / 4);
    #pragma unroll 4
    for (int h = h0; h < h0 + HID / 4; ++h)
        acc = fmaf(sx[h], rw[h * NEXP + lane], acc);
    spart[w][lane] = acc;
    __syncthreads();
    if (tid < NEXP)
        slog[tid] = spart[0][tid] + spart[1][tid] + spart[2][tid] + spart[3][tid];
    __syncthreads();

    if (tid == 0) {
        float sc[NEXP], sb[NEXP];
        #pragma unroll
        for (int e = 0; e < NEXP; ++e) {
            float s = 1.f / (1.f + expf(-slog[e]));
            sc[e] = s;
            sb[e] = s + rbias[e];
        }
        float gs[NGRP];
        #pragma unroll
        for (int g = 0; g < NGRP; ++g) {
            float m1 = -1e30f, m2 = -1e30f;
            #pragma unroll
            for (int j = 0; j < EPG; ++j) {
                float v = sb[g * EPG + j];
                if (v > m1) { m2 = m1; m1 = v; }
                else if (v > m2) { m2 = v; }
            }
            gs[g] = m1 + m2;
        }
        bool keep[NGRP];
        #pragma unroll
        for (int g = 0; g < NGRP; ++g) keep[g] = false;
        for (int r = 0; r < TKG; ++r) {
            int bi = -1; float bv = -1e30f;
            for (int g = 0; g < NGRP; ++g)
                if (!keep[g] && gs[g] > bv) { bv = gs[g]; bi = g; }
            keep[bi] = true;
        }
        float masked[NEXP];
        #pragma unroll
        for (int e = 0; e < NEXP; ++e)
            masked[e] = keep[e >> 2] ? sb[e] : 0.0f;
        int idx[TOPK];
        for (int r = 0; r < TOPK; ++r) {
            int bi = 0; float bv = -1e30f;
            for (int e = 0; e < NEXP; ++e)
                if (masked[e] > bv) { bv = masked[e]; bi = e; }
            masked[bi] = -1e30f;
            idx[r] = bi;
        }
        float wsum = 0.f, wv[TOPK];
        #pragma unroll
        for (int r = 0; r < TOPK; ++r) { wv[r] = sc[idx[r]]; wsum += wv[r]; }
        float inv = ROUTED_SCALE / wsum;
        #pragma unroll
        for (int r = 0; r < TOPK; ++r) {
            g_tkidx[t * TOPK + r] = idx[r];
            g_tkw  [t * TOPK + r] = wv[r] * inv;
        }
    }
}

// ---------------- fused dispatch ----------------
__global__ void __launch_bounds__(1024)
dispatch_kernel()
{
    __shared__ int sc[NEXP], so[NEXP], scur[NEXP];
    int tid = threadIdx.x;
    if (tid < NEXP) { sc[tid] = 0; scur[tid] = 0; }
    __syncthreads();
    for (int i = tid; i < NROW; i += 1024)
        atomicAdd(&sc[g_tkidx[i]], 1);
    __syncthreads();
    if (tid == 0) {
        int a = 0;
        #pragma unroll
        for (int e = 0; e < NEXP; ++e) { so[e] = a; a += sc[e]; }
    }
    __syncthreads();
    for (int i = tid; i < NROW; i += 1024) {
        int e = g_tkidx[i];
        int pos = so[e] + atomicAdd(&scur[e], 1);
        g_row_token[pos] = i >> 3;
        g_inv[i] = pos;
    }
    if (tid < NEXP) { g_counts[tid] = sc[tid]; g_offsets[tid] = so[tid]; }
}

// ---------------- tf32 tensor-core GEMM ----------------
// 256 threads = 8 warps, block 256x128x32, warp tile 64x64.
// 3-stage cp.async; A fragments via ldmatrix.x4; operands pre-rounded tf32.
#define BM 256
#define BN 128
#define BK 32
#define AS_STRIDE 36
#define AS_BUF (BM * AS_STRIDE)      // 9216 words
#define BS_BUF (BK * BN)             // 4096 words
#define NSTAGE 3
#define GEMM_SMEM_W (256 + NSTAGE * (AS_BUF + BS_BUF))   // 40192 w = 160768 B

__global__ void __launch_bounds__(256)
tmma_kernel(const float* __restrict__ A,
            const float* __restrict__ B1p, const float* __restrict__ B2p,
            float* __restrict__ C1p, float* __restrict__ C2p,
            int Nhalf, int Kd, int grouped, int gather, int Mtotal)
{
    extern __shared__ uint32_t smu[];
    int* sArow = (int*)smu;
    uint32_t* Asb = smu + 256;
    uint32_t* Bsb = smu + 256 + NSTAGE * AS_BUF;
#define BSW(b, k, n) Bsb[(b) * BS_BUF + (k) * BN + ((n) ^ ((((k) & 3)) << 3))]

    int tid = threadIdx.x;
    int e = blockIdx.z;
    int off, cnt;
    if (grouped) { off = g_offsets[e]; cnt = g_counts[e]; }
    else         { off = 0;            cnt = Mtotal; }
    int mtile = blockIdx.y * BM;
    if (mtile >= cnt) return;

    int n0 = blockIdx.x * BN;
    const float* B0 = B1p; float* C = C1p;
    if (n0 >= Nhalf) { B0 = B2p; C = C2p; n0 -= Nhalf; }
    const int N = Nhalf;

    {
        int lr = mtile + tid;
        if (lr >= cnt) lr = cnt - 1;
        int p = off + lr;
        sArow[tid] = gather ? g_row_token[p] : p;
    }
    __syncthreads();

    const float* Bg = B0 + (size_t)e * Kd * N + n0;

    // A loader: rows (tid>>1), (tid>>1)+128; seg (tid&1)*16
    int ar = tid >> 1;
    int aseg = (tid & 1) * 16;
    const float* Ap0 = A + (size_t)sArow[ar] * Kd + aseg;
    const float* Ap1 = A + (size_t)sArow[ar + 128] * Kd + aseg;
    // B loader: k rows (tid>>5)+8j, float4 at col (tid&31)*4
    int bk = tid >> 5;
    int bcol = (tid & 31) * 4;
    int bswz = bcol ^ ((bk & 3) << 3);

    uint32_t sb = smem_u32(smu);
    uint32_t asb_base = sb + 256u * 4u;                    // byte addr of Asb
    uint32_t aA0 = asb_base + ((uint32_t)ar * AS_STRIDE + aseg) * 4u;
    uint32_t aA1 = aA0 + 128u * AS_STRIDE * 4u;
    uint32_t bA  = sb + (256u + NSTAGE * AS_BUF) * 4u + ((uint32_t)bk * BN + bswz) * 4u;
    const float* Bp = Bg + (size_t)bk * N + bcol;

    int numK = Kd >> 5;

    // prologue: stages 0,1
    #pragma unroll
    for (int s = 0; s < 2; ++s) {
        int ko = s << 5;
        #pragma unroll
        for (int j = 0; j < 4; ++j) {
            cp16(aA0 + (uint32_t)s * AS_BUF * 4 + j * 16, Ap0 + ko + j * 4);
            cp16(aA1 + (uint32_t)s * AS_BUF * 4 + j * 16, Ap1 + ko + j * 4);
            cp16(bA  + (uint32_t)s * BS_BUF * 4 + (uint32_t)j * 8 * BN * 4,
                 Bp + (size_t)(ko + 8 * j) * N);
        }
        CP_COMMIT();
    }

    int wid = tid >> 5, lane = tid & 31;
    int wm = wid >> 1, wn = wid & 1;
    int g = lane >> 2, tg = lane & 3;

    // ldmatrix lane geometry for A fragments:
    // matrix sub = lane>>3: row += (sub&1)*8, word += (sub>>1)*4
    uint32_t a_row_lane  = (uint32_t)(((lane >> 3) & 1) * 8 + (lane & 7));
    uint32_t a_word_lane = (uint32_t)((lane >> 4) * 4);
    // per-mi byte address base (without buf/k8): (row_total*36 + word)*4
    uint32_t a_addr_mi[4];
    #pragma unroll
    for (int mi = 0; mi < 4; ++mi)
        a_addr_mi[mi] = asb_base +
            (((uint32_t)(wm * 64 + mi * 16) + a_row_lane) * AS_STRIDE + a_word_lane) * 4u;

    float acc[4][8][4];
    #pragma unroll
    for (int mi = 0; mi < 4; ++mi)
        #pragma unroll
        for (int ni = 0; ni < 8; ++ni)
            #pragma unroll
            for (int c = 0; c < 4; ++c) acc[mi][ni][c] = 0.f;

    int buf = 0, nbuf = 2;
    for (int t = 0; t < numK; ++t) {
        if (t + 1 < numK) { CP_WAIT1(); } else { CP_WAIT0(); }
        __syncthreads();
        if (t + 2 < numK) {
            int ko = (t + 2) << 5;
            #pragma unroll
            for (int j = 0; j < 4; ++j) {
                cp16(aA0 + (uint32_t)nbuf * AS_BUF * 4 + j * 16, Ap0 + ko + j * 4);
                cp16(aA1 + (uint32_t)nbuf * AS_BUF * 4 + j * 16, Ap1 + ko + j * 4);
                cp16(bA  + (uint32_t)nbuf * BS_BUF * 4 + (uint32_t)j * 8 * BN * 4,
                     Bp + (size_t)(ko + 8 * j) * N);
            }
            CP_COMMIT();
        }
        uint32_t buf_off = (uint32_t)buf * AS_BUF * 4u;
        #pragma unroll
        for (int kk = 0; kk < 4; ++kk) {
            int k8 = kk * 8;
            uint32_t af[4][4];
            #pragma unroll
            for (int mi = 0; mi < 4; ++mi)
                ldsm4(af[mi], a_addr_mi[mi] + buf_off + (uint32_t)k8 * 4u);
            uint32_t bf[8][2];
            #pragma unroll
            for (int ni = 0; ni < 8; ++ni) {
                int nn = wn * 64 + ni * 8 + g;
                bf[ni][0] = BSW(buf, k8 + tg,     nn);
                bf[ni][1] = BSW(buf, k8 + tg + 4, nn);
            }
            #pragma unroll
            for (int mi = 0; mi < 4; ++mi)
                #pragma unroll
                for (int ni = 0; ni < 8; ++ni)
                    mma_tf32(acc[mi][ni], af[mi], bf[ni]);
        }
        if (++buf == NSTAGE) buf = 0;
        if (++nbuf == NSTAGE) nbuf = 0;
    }

    // epilogue
    #pragma unroll
    for (int mi = 0; mi < 4; ++mi) {
        int lr0 = mtile + wm * 64 + mi * 16 + g;
        #pragma unroll
        for (int ni = 0; ni < 8; ++ni) {
            int col = n0 + wn * 64 + ni * 8 + tg * 2;
            if (lr0 < cnt)
                *(float2*)(C + (size_t)(off + lr0) * N + col) =
                    make_float2(acc[mi][ni][0], acc[mi][ni][1]);
            if (lr0 + 8 < cnt)
                *(float2*)(C + (size_t)(off + lr0 + 8) * N + col) =
                    make_float2(acc[mi][ni][2], acc[mi][ni][3]);
        }
    }
#undef BSW
}

// ---------------- SwiGLU elementwise -> tf32-rounded output ----------------
__global__ void silu_mul_round_kernel(float* __restrict__ g, const float* __restrict__ u,
                                      long n4)
{
    long i = (long)blockIdx.x * blockDim.x + threadIdx.x;
    long stride = (long)gridDim.x * blockDim.x;
    uint4* gv = (uint4*)g;
    const float4* gf = (const float4*)g;
    const float4* uv = (const float4*)u;
    for (; i < n4; i += stride) {
        float4 gg = gf[i];
        float4 uu = uv[i];
        float vx = gg.x / (1.f + __expf(-gg.x)) * uu.x;
        float vy = gg.y / (1.f + __expf(-gg.y)) * uu.y;
        float vz = gg.z / (1.f + __expf(-gg.z)) * uu.z;
        float vw = gg.w / (1.f + __expf(-gg.w)) * uu.w;
        gv[i] = make_uint4(f2tf(vx), f2tf(vy), f2tf(vz), f2tf(vw));
    }
}

// ---------------- combine ----------------
__global__ void combine_kernel(const float* __restrict__ down, float* __restrict__ out)
{
    int t = blockIdx.x;
    int tid = threadIdx.x;
    int   pidx[TOPK];
    float pw[TOPK];
    #pragma unroll
    for (int k = 0; k < TOPK; ++k) {
        pidx[k] = g_inv[t * TOPK + k];
        pw[k]   = g_tkw[t * TOPK + k];
    }
    const int H4 = HID / 4;
    float4* ov = (float4*)out;
    const float4* dv = (const float4*)down;
    for (int i = tid; i < H4; i += 256) {
        float4 o = ov[(size_t)t * H4 + i];
        #pragma unroll
        for (int k = 0; k < TOPK; ++k) {
            float4 v = dv[(size_t)pidx[k] * H4 + i];
            float w = pw[k];
            o.x = fmaf(w, v.x, o.x);
            o.y = fmaf(w, v.y, o.y);
            o.z = fmaf(w, v.z, o.z);
            o.w = fmaf(w, v.w, o.w);
        }
        ov[(size_t)t * H4 + i] = o;
    }
}

// ---------------- launch ----------------
static float* symf(const void* sym) {
    void* p = nullptr;
    cudaGetSymbolAddress(&p, sym);
    return (float*)p;
}

extern "C" void kernel_launch(void* const* d_in, const int* in_sizes, int n_in,
                              void* d_out, int out_size)
{
    const float* x       = (const float*)d_in[0];
    const float* rw      = (const float*)d_in[1];
    const float* rbias   = (const float*)d_in[2];
    const float* w_gate  = (const float*)d_in[3];
    const float* w_up    = (const float*)d_in[4];
    const float* w_down  = (const float*)d_in[5];
    const float* sw_gate = (const float*)d_in[6];
    const float* sw_up   = (const float*)d_in[7];
    const float* sw_down = (const float*)d_in[8];
    float* out = (float*)d_out;

    float* p_gate = symf(g_gate);
    float* p_up   = symf(g_up);
    float* p_down = symf(g_down);
    float* p_sg   = symf(g_sg);
    float* p_su   = symf(g_su);
    float* p_rwg  = symf(g_rwg);
    float* p_rwu  = symf(g_rwu);
    float* p_rwd  = symf(g_rwd);
    float* p_rsg  = symf(g_rsg);
    float* p_rsu  = symf(g_rsu);
    float* p_rsd  = symf(g_rsd);
    float* p_rx   = symf(g_rx);

    const int SMB = GEMM_SMEM_W * 4;
    cudaFuncSetAttribute(tmma_kernel, cudaFuncAttributeMaxDynamicSharedMemorySize, SMB);

    // 0) pre-round all GEMM operands
    round_all_kernel<<<2048, 256>>>(w_gate, w_up, w_down, sw_gate, sw_up, sw_down, x);

    // 1) router + dispatch
    router_kernel<<<TOK, 128>>>(x, rw, rbias);
    dispatch_kernel<<<1, 1024>>>();

    // 2) routed gate+up fused (A gathered from rounded x), N=1024 each
    tmma_kernel<<<dim3(16, 16, NEXP), 256, SMB>>>(
        p_rx, p_rwg, p_rwu, p_gate, p_up, IDIM, HID, 1, 1, 0);

    // 3) SwiGLU (rounded output, in place)
    silu_mul_round_kernel<<<2048, 256>>>(p_gate, p_up, (long)NROW * IDIM / 4);

    // 4) routed down: N=2048, K=1024  (ncu launch #5)
    tmma_kernel<<<dim3(16, 16, NEXP), 256, SMB>>>(
        p_gate, p_rwd, p_rwd, p_down, p_down, HID, IDIM, 1, 0, 0);

    // 5) shared gate+up fused: N=2048 each
    tmma_kernel<<<dim3(32, 16, 1), 256, SMB>>>(
        p_rx, p_rsg, p_rsu, p_sg, p_su, SDIM, HID, 0, 0, TOK);
    silu_mul_round_kernel<<<2048, 256>>>(p_sg, p_su, (long)TOK * SDIM / 4);
    tmma_kernel<<<dim3(16, 16, 1), 256, SMB>>>(
        p_sg, p_rsd, p_rsd, out, out, HID, SDIM, 0, 0, TOK);

    // 6) weighted combine
    combine_kernel<<<TOK, 256>>>(p_down, out);
}